// round 16
// baseline (speedup 1.0000x reference)
#include <cuda_runtime.h>
#include <cuda_fp16.h>
#include <math.h>
#include <stdint.h>

#define Bb 4
#define Nn 16384
#define Mm 1024
#define Cc 256
#define Kk 32
#define Pp (Bb*Mm*Kk)
#define COUT 512

#define SUM1 0
#define SQ1  128
#define SUM2 256
#define SQ2  260
#define SUML0 264
#define NSTATS (264 + 3*1024)

__device__ __align__(128) __half g_featTh[(size_t)Bb*Nn*Cc];
__device__ __align__(128) __half g_G[(size_t)Bb*Nn*COUT];
__device__ __align__(128) __half g_Y1[(size_t)Pp*COUT];
__device__ __align__(128) __half g_Y2[(size_t)Pp*COUT];
__device__ __align__(128) float  g_mx[(size_t)Bb*Mm*COUT];
__device__ __align__(128) float  g_mn[(size_t)Bb*Mm*COUT];
__device__ __align__(128) float  g_h1[Bb*128*Mm];
__device__ __align__(128) float  g_h2[Bb*3*Mm];
__device__ __align__(128) float  g_q[Bb*Mm*3];
__device__ __align__(128) int    g_idx[Pp];
__device__ __align__(128) __half g_W1h[COUT*Cc];
__device__ __align__(128) float  g_W1x[3*COUT];
__device__ __align__(128) __half g_W2h[COUT*COUT];
__device__ __align__(128) __half g_W3h[COUT*COUT];
__device__ __align__(128) float  g_stats[NSTATS];
__device__ float g_sc1[128], g_bi1[128];
__device__ float g_sc2[4],   g_bi2[4];

// side stream + fork/join events, created once before harness checkpoints
struct SideStream {
    cudaStream_t s;
    cudaEvent_t evF, evP, evJ;
    SideStream() {
        cudaStreamCreateWithFlags(&s, cudaStreamNonBlocking);
        cudaEventCreateWithFlags(&evF, cudaEventDisableTiming);
        cudaEventCreateWithFlags(&evP, cudaEventDisableTiming);
        cudaEventCreateWithFlags(&evJ, cudaEventDisableTiming);
    }
};
static SideStream g_side;

__device__ __forceinline__ float wredsum(float v) {
    #pragma unroll
    for (int o = 16; o > 0; o >>= 1) v += __shfl_xor_sync(0xFFFFFFFFu, v, o);
    return v;
}
__device__ __forceinline__ uint32_t packh2(float a, float b) {
    __half2 h = __floats2half2_rn(a, b);
    return *(uint32_t*)&h;
}
__device__ __forceinline__ uint32_t smem_u32(const void* p) {
    uint32_t a;
    asm("{ .reg .u64 t; cvta.to.shared.u64 t, %1; cvt.u32.u64 %0, t; }" : "=r"(a) : "l"(p));
    return a;
}
__device__ __forceinline__ void mma_f16(float* d, const uint32_t* a, const uint32_t* b) {
    asm volatile("mma.sync.aligned.m16n8k16.row.col.f32.f16.f16.f32 "
                 "{%0,%1,%2,%3}, {%4,%5,%6,%7}, {%8,%9}, {%0,%1,%2,%3};"
                 : "+f"(d[0]), "+f"(d[1]), "+f"(d[2]), "+f"(d[3])
                 : "r"(a[0]), "r"(a[1]), "r"(a[2]), "r"(a[3]), "r"(b[0]), "r"(b[1]));
}
__device__ __forceinline__ void ldsm_x4(uint32_t& r0, uint32_t& r1, uint32_t& r2, uint32_t& r3, uint32_t addr) {
    asm volatile("ldmatrix.sync.aligned.m8n8.x4.shared.b16 {%0,%1,%2,%3}, [%4];"
                 : "=r"(r0), "=r"(r1), "=r"(r2), "=r"(r3) : "r"(addr));
}
__device__ __forceinline__ void cpa16(uint32_t dst, const void* src) {
    asm volatile("cp.async.cg.shared.global [%0], [%1], 16;" :: "r"(dst), "l"(src));
}
#define CPA_COMMIT() asm volatile("cp.async.commit_group;" ::: "memory")
#define CPA_WAIT1()  asm volatile("cp.async.wait_group 1;" ::: "memory")

__global__ void k_zero() {
    int i = blockIdx.x * blockDim.x + threadIdx.x;
    if (i < NSTATS) g_stats[i] = 0.f;
}

// prep: repack w1 (split feat/xyz) + convert w2/w3 to fp16
__global__ void k_prep(const float* __restrict__ w1, const float* __restrict__ w2,
                       const float* __restrict__ w3) {
    int i = blockIdx.x * blockDim.x + threadIdx.x;
    if (i < COUT * Cc) {
        int o = i >> 8, c = i & 255;
        g_W1h[i] = __float2half(w1[o * 259 + 3 + c]);
    }
    if (i < 3 * COUT) {
        int d = i / COUT, o = i % COUT;
        g_W1x[d * COUT + o] = w1[o * 259 + d];
    }
    if (i < COUT * COUT) {
        g_W2h[i] = __float2half(w2[i]);
        g_W3h[i] = __float2half(w3[i]);
    }
}

// grid (128, 2): blk.x = b(4)*mtile(32), blk.y = o-half; 256 thr
__global__ void k_s1(const float* __restrict__ feat, const float* __restrict__ sw1) {
    int blk = blockIdx.x;
    int b = blk >> 5;
    int m0 = (blk & 31) * 32;
    int ob = blockIdx.y * 64;
    int tid = threadIdx.x;
    int mx = tid & 31, oy = tid >> 5;
    __shared__ float s_w[64][17];
    __shared__ float s_f[16][33];
    float acc[8];
    #pragma unroll
    for (int r = 0; r < 8; r++) acc[r] = 0.f;
    for (int c0 = 0; c0 < 256; c0 += 16) {
        __syncthreads();
        for (int idx = tid; idx < 64 * 16; idx += 256) {
            int ol = idx >> 4, kk = idx & 15;
            s_w[ol][kk] = sw1[(ob + ol) * 256 + c0 + kk];
        }
        for (int idx = tid; idx < 16 * 32; idx += 256) {
            int kk = idx >> 5, mm = idx & 31;
            s_f[kk][mm] = feat[((size_t)b * 256 + c0 + kk) * Mm + m0 + mm];
        }
        __syncthreads();
        #pragma unroll
        for (int r = 0; r < 8; r++) {
            int ol = oy * 8 + r;
            #pragma unroll
            for (int kk = 0; kk < 16; kk++) acc[r] += s_w[ol][kk] * s_f[kk][mx];
        }
    }
    #pragma unroll
    for (int r = 0; r < 8; r++) {
        int o = ob + oy * 8 + r;
        float v = acc[r];
        g_h1[((size_t)b * 128 + o) * Mm + m0 + mx] = v;
        float s = wredsum(v), s2 = wredsum(v * v);
        if (mx == 0) {
            atomicAdd(&g_stats[SUM1 + o], s);
            atomicAdd(&g_stats[SQ1 + o], s2);
        }
    }
}

__global__ void k_fin(int n, int sumOff, int sqOff,
                      const float* __restrict__ gamma, const float* __restrict__ beta,
                      int which, float count) {
    int i = blockIdx.x * blockDim.x + threadIdx.x;
    if (i >= n) return;
    float mean = g_stats[sumOff + i] / count;
    float var  = g_stats[sqOff + i] / count - mean * mean;
    var = fmaxf(var, 0.f);
    float s = gamma[i] * rsqrtf(var + 1e-5f);
    float bi = beta[i] - mean * s;
    if (which == 0) { g_sc1[i] = s; g_bi1[i] = bi; }
    else            { g_sc2[i] = s; g_bi2[i] = bi; }
}

// grid 128 (b*mtile32), 256 thr: 8 o-groups of 16 x 32 m; smem reduce
__global__ void k_s2(const float* __restrict__ sw2) {
    int blk = blockIdx.x;
    int b = blk >> 5;
    int m0 = (blk & 31) * 32;
    int tid = threadIdx.x;
    int mx = tid & 31, og = tid >> 5;
    __shared__ float s_w[3][128];
    __shared__ float red[3][8][33];
    for (int i = tid; i < 384; i += 256) s_w[i >> 7][i & 127] = sw2[i];
    __syncthreads();
    float a0 = 0.f, a1 = 0.f, a2 = 0.f;
    #pragma unroll
    for (int oo = 0; oo < 16; oo++) {
        int o = og * 16 + oo;
        float h = g_h1[((size_t)b * 128 + o) * Mm + m0 + mx];
        float x = fmaxf(h * g_sc1[o] + g_bi1[o], 0.f);
        a0 += s_w[0][o] * x;
        a1 += s_w[1][o] * x;
        a2 += s_w[2][o] * x;
    }
    red[0][og][mx] = a0;
    red[1][og][mx] = a1;
    red[2][og][mx] = a2;
    __syncthreads();
    if (og < 3) {
        float tt = 0.f;
        #pragma unroll
        for (int w = 0; w < 8; w++) tt += red[og][w][mx];
        int m = m0 + mx;
        g_h2[((size_t)b * 3 + og) * Mm + m] = tt;
        float s = wredsum(tt), ss = wredsum(tt * tt);
        if (mx == 0) {
            atomicAdd(&g_stats[SUM2 + og], s);
            atomicAdd(&g_stats[SQ2 + og], ss);
        }
    }
}

__global__ void k_neigh(const float* __restrict__ fxyz, const float* __restrict__ bxyz) {
    int bm = blockIdx.x;
    int b = bm >> 10;
    int m = bm & 1023;
    int tid = threadIdx.x;
    __shared__ float q[3];
    __shared__ int list[Kk];
    __shared__ int cnt;
    __shared__ unsigned masks[8];
    if (tid == 0) cnt = 0;
    if (tid < 3) {
        float h = g_h2[((size_t)b * 3 + tid) * Mm + m];
        float sft = fmaxf(h * g_sc2[tid] + g_bi2[tid], 0.f);
        float qq = fxyz[((size_t)b * Mm + m) * 3 + tid] + sft;
        q[tid] = qq;
        g_q[((size_t)b * Mm + m) * 3 + tid] = qq;
    }
    __syncthreads();
    float qx = q[0], qy = q[1], qz = q[2];
    const float* bx = bxyz + (size_t)b * Nn * 3;
    int lane = tid & 31, wid = tid >> 5;
    for (int ch = 0; ch < Nn / 256; ch++) {
        int j = ch * 256 + tid;
        float dx = bx[j * 3 + 0] - qx;
        float dy = bx[j * 3 + 1] - qy;
        float dz = bx[j * 3 + 2] - qz;
        bool p = (dx * dx + dy * dy + dz * dz) < 1.0f;
        unsigned mk = __ballot_sync(0xFFFFFFFFu, p);
        if (lane == 0) masks[wid] = mk;
        __syncthreads();
        int before = cnt;
        for (int w = 0; w < wid; w++) before += __popc(masks[w]);
        if (p) {
            int pos = before + __popc(mk & ((1u << lane) - 1u));
            if (pos < Kk) list[pos] = j;
        }
        int total = 0;
        #pragma unroll
        for (int w = 0; w < 8; w++) total += __popc(masks[w]);
        __syncthreads();
        if (tid == 0) cnt += total;
        __syncthreads();
        if (cnt >= Kk) break;
    }
    if (tid < Kk) {
        int c = cnt;
        int v;
        if (c == 0)        v = 0;
        else if (tid < c)  v = list[tid];
        else               v = list[0];
        g_idx[bm * Kk + tid] = v;
    }
}

// transpose (B,C,N) f32 -> (B,N,C) fp16, half2 stores
__global__ void k_transpose(const float* __restrict__ bf) {
    __shared__ float t[32][33];
    int b = blockIdx.z;
    int j0 = blockIdx.x * 32;
    int c0 = blockIdx.y * 32;
    int x = threadIdx.x, y = threadIdx.y;
    #pragma unroll
    for (int yy = y; yy < 32; yy += 8)
        t[yy][x] = bf[((size_t)b * Cc + c0 + yy) * Nn + j0 + x];
    __syncthreads();
    int tid = y * 32 + x;
    #pragma unroll
    for (int idx = tid; idx < 32 * 16; idx += 256) {
        int j = idx >> 4, cp = idx & 15;
        __half2 h = __floats2half2_rn(t[cp * 2][j], t[cp * 2 + 1][j]);
        *(__half2*)(g_featTh + ((size_t)b * Nn + j0 + j) * Cc + c0 + cp * 2) = h;
    }
}

// gather-add: Y0[p,:] = G[b,j_p,:] + W1x @ dx; BN0 stats fused
__global__ void k_gat(const float* __restrict__ bxyz) {
    int bm = blockIdx.x;
    int b = bm >> 10;
    int tid = threadIdx.x;
    __shared__ int jl[Kk];
    __shared__ float dxs[3][Kk];
    if (tid < Kk) {
        int j = g_idx[bm * Kk + tid];
        jl[tid] = j;
        const float* bx = bxyz + ((size_t)b * Nn + j) * 3;
        dxs[0][tid] = bx[0] - g_q[bm * 3 + 0];
        dxs[1][tid] = bx[1] - g_q[bm * 3 + 1];
        dxs[2][tid] = bx[2] - g_q[bm * 3 + 2];
    }
    __syncthreads();
    float2 wx0 = *(const float2*)&g_W1x[0 * COUT + 2 * tid];
    float2 wx1 = *(const float2*)&g_W1x[1 * COUT + 2 * tid];
    float2 wx2 = *(const float2*)&g_W1x[2 * COUT + 2 * tid];
    float s0 = 0.f, s1 = 0.f, q20 = 0.f, q21 = 0.f;
    #pragma unroll 4
    for (int k = 0; k < Kk; k++) {
        int j = jl[k];
        __half2 gh = *(const __half2*)(g_G + (((size_t)b * Nn + j) << 9) + 2 * tid);
        float2 gf = __half22float2(gh);
        float d0 = dxs[0][k], d1 = dxs[1][k], d2 = dxs[2][k];
        float y0 = gf.x + wx0.x * d0 + wx1.x * d1 + wx2.x * d2;
        float y1 = gf.y + wx0.y * d0 + wx1.y * d1 + wx2.y * d2;
        *(uint32_t*)(g_Y1 + (((size_t)(bm * Kk + k)) << 9) + 2 * tid) = packh2(y0, y1);
        s0 += y0; s1 += y1;
        q20 += y0 * y0; q21 += y1 * y1;
    }
    atomicAdd(&g_stats[SUML0 + 2 * tid],       s0);
    atomicAdd(&g_stats[SUML0 + 2 * tid + 1],   s1);
    atomicAdd(&g_stats[SUML0 + 512 + 2 * tid],     q20);
    atomicAdd(&g_stats[SUML0 + 512 + 2 * tid + 1], q21);
}

#define NSTG 3
#define LD2 20
#define STGW (128 * LD2)

// f32-acc GEMM. LAYER 0: G = featTh @ W1h^T (no BN in, no stats out).
// LAYER 1: Y2 = relu(bn0(Y1)) @ W2^T.
// LAYER 2: per-(bm,col) max/min of relu(bn1(Y2)) @ W3^T  (no Y store).
template <int LAYER>
__global__ void __launch_bounds__(256, 2) k_mma(const float* __restrict__ gamPrev,
                                                const float* __restrict__ betPrev) {
    constexpr int CIN = (LAYER == 0) ? Cc : COUT;
    constexpr int NCH = CIN / 32;
    constexpr int sumOff = SUML0 + LAYER * 1024;
    constexpr int sqOff  = sumOff + 512;
    const __half* Ah = (LAYER == 0) ? g_featTh : (LAYER == 1 ? g_Y1 : g_Y2);
    __half*       Y  = (LAYER == 0) ? g_G     : g_Y2;
    const __half* W  = (LAYER == 0) ? g_W1h   : (LAYER == 1 ? g_W2h : g_W3h);

    extern __shared__ uint32_t dyn[];
    uint32_t* sA   = dyn;
    uint32_t* sB   = dyn + NSTG * STGW;
    uint32_t* sSc2 = dyn + 2 * NSTG * STGW;
    uint32_t* sBi2 = sSc2 + 256;
    float*    sPs  = (float*)(sBi2 + 256);
    float*    sPq  = sPs + 128;

    int tid = threadIdx.x;
    int lane = tid & 31, wrp = tid >> 5;
    int g = lane >> 2, t = lane & 3;
    int wm = wrp & 3, wn = wrp >> 2;
    int row0 = blockIdx.y * 128;
    int col0 = blockIdx.x * 128;

    if (LAYER > 0) {
        const float invP = 1.f / (float)Pp;
        int pOff = SUML0 + (LAYER - 1) * 1024;
        for (int cp = tid; cp < 256; cp += 256) {
            int c0 = cp * 2, c1 = cp * 2 + 1;
            float m0 = g_stats[pOff + c0] * invP;
            float v0 = fmaxf(g_stats[pOff + 512 + c0] * invP - m0 * m0, 0.f);
            float s0 = gamPrev[c0] * rsqrtf(v0 + 1e-5f);
            float m1 = g_stats[pOff + c1] * invP;
            float v1 = fmaxf(g_stats[pOff + 512 + c1] * invP - m1 * m1, 0.f);
            float s1 = gamPrev[c1] * rsqrtf(v1 + 1e-5f);
            sSc2[cp] = packh2(s0, s1);
            sBi2[cp] = packh2(betPrev[c0] - m0 * s0, betPrev[c1] - m1 * s1);
        }
        if (tid < 128) { sPs[tid] = 0.f; sPq[tid] = 0.f; }
        __syncthreads();
    }

    int r0 = tid >> 2, q0 = tid & 3;
    int r1 = r0 + 64;
    const char* aSrc0 = (const char*)(Ah + (size_t)(row0 + r0) * CIN) + q0 * 16;
    const char* aSrc1 = (const char*)(Ah + (size_t)(row0 + r1) * CIN) + q0 * 16;
    const char* bSrc0 = (const char*)(W + (size_t)(col0 + r0) * CIN) + q0 * 16;
    const char* bSrc1 = (const char*)(W + (size_t)(col0 + r1) * CIN) + q0 * 16;
    uint32_t sbA = smem_u32(sA), sbB = smem_u32(sB);
    uint32_t aDst0 = sbA + (r0 * LD2 + q0 * 4) * 4;
    uint32_t aDst1 = sbA + (r1 * LD2 + q0 * 4) * 4;
    uint32_t bDst0 = sbB + (r0 * LD2 + q0 * 4) * 4;
    uint32_t bDst1 = sbB + (r1 * LD2 + q0 * 4) * 4;

    uint32_t aoff[2], boff[4];
    #pragma unroll
    for (int i = 0; i < 2; i++)
        aoff[i] = ((wm * 32 + i * 16 + (lane & 15)) * LD2 + (lane >> 4) * 4) * 4;
    #pragma unroll
    for (int jp = 0; jp < 4; jp++)
        boff[jp] = ((wn * 64 + jp * 16 + ((lane >> 4) & 1) * 8 + (lane & 7)) * LD2
                    + ((lane >> 3) & 1) * 4) * 4;

    float acc[2][8][4];
    #pragma unroll
    for (int i = 0; i < 2; i++)
        #pragma unroll
        for (int j = 0; j < 8; j++)
            #pragma unroll
            for (int rr = 0; rr < 4; rr++) acc[i][j][rr] = 0.f;

    auto fill = [&](int c) {
        int s = c % NSTG;
        uint32_t so = (uint32_t)s * (STGW * 4);
        cpa16(aDst0 + so, aSrc0 + c * 64);
        cpa16(aDst1 + so, aSrc1 + c * 64);
        cpa16(bDst0 + so, bSrc0 + c * 64);
        cpa16(bDst1 + so, bSrc1 + c * 64);
    };

    const __half2 z2 = __float2half2_rn(0.f);
    fill(0); CPA_COMMIT();
    fill(1); CPA_COMMIT();

    for (int c = 0; c < NCH; c++) {
        CPA_WAIT1();
        __syncthreads();
        int s = c % NSTG;
        uint32_t aB = sbA + (uint32_t)s * (STGW * 4);
        uint32_t bB = sbB + (uint32_t)s * (STGW * 4);
        uint32_t scw[2][2], biw[2][2];
        if (LAYER > 0) {
            #pragma unroll
            for (int ks = 0; ks < 2; ks++)
                #pragma unroll
                for (int sub = 0; sub < 2; sub++) {
                    int idx = c * 16 + ks * 8 + sub * 4 + t;
                    scw[ks][sub] = sSc2[idx];
                    biw[ks][sub] = sBi2[idx];
                }
        }
        #pragma unroll
        for (int ks = 0; ks < 2; ks++) {
            uint32_t af[2][4], bf[8][2];
            #pragma unroll
            for (int i = 0; i < 2; i++)
                ldsm_x4(af[i][0], af[i][1], af[i][2], af[i][3], aB + aoff[i] + ks * 32);
            #pragma unroll
            for (int jp = 0; jp < 4; jp++)
                ldsm_x4(bf[jp * 2][0], bf[jp * 2][1], bf[jp * 2 + 1][0], bf[jp * 2 + 1][1],
                        bB + boff[jp] + ks * 32);
            if (LAYER > 0) {
                #pragma unroll
                for (int i = 0; i < 2; i++)
                    #pragma unroll
                    for (int rr = 0; rr < 4; rr++) {
                        int sub = rr >> 1;
                        __half2 h = *(__half2*)&af[i][rr];
                        h = __hmax2(__hfma2(h, *(__half2*)&scw[ks][sub], *(__half2*)&biw[ks][sub]), z2);
                        af[i][rr] = *(uint32_t*)&h;
                    }
            }
            #pragma unroll
            for (int i = 0; i < 2; i++)
                #pragma unroll
                for (int j = 0; j < 8; j++)
                    mma_f16(acc[i][j], af[i], bf[j]);
        }
        if (c + 2 < NCH) fill(c + 2);
        CPA_COMMIT();
    }

    if (LAYER != 2) {
        #pragma unroll
        for (int i = 0; i < 2; i++) {
            int rlo = row0 + wm * 32 + i * 16 + g;
            #pragma unroll
            for (int j = 0; j < 8; j++) {
                int col = col0 + wn * 64 + j * 8 + t * 2;
                *(uint32_t*)(Y + (size_t)rlo * COUT + col)       = packh2(acc[i][j][0], acc[i][j][1]);
                *(uint32_t*)(Y + (size_t)(rlo + 8) * COUT + col) = packh2(acc[i][j][2], acc[i][j][3]);
            }
        }
    } else {
        int bm = blockIdx.y * 4 + wm;
        #pragma unroll
        for (int j = 0; j < 8; j++) {
            #pragma unroll
            for (int rb = 0; rb < 2; rb++) {
                float mx = fmaxf(fmaxf(acc[0][j][rb], acc[0][j][rb + 2]),
                                 fmaxf(acc[1][j][rb], acc[1][j][rb + 2]));
                float mn = fminf(fminf(acc[0][j][rb], acc[0][j][rb + 2]),
                                 fminf(acc[1][j][rb], acc[1][j][rb + 2]));
                mx = fmaxf(mx, __shfl_xor_sync(0xFFFFFFFFu, mx, 4));
                mn = fminf(mn, __shfl_xor_sync(0xFFFFFFFFu, mn, 4));
                mx = fmaxf(mx, __shfl_xor_sync(0xFFFFFFFFu, mx, 8));
                mn = fminf(mn, __shfl_xor_sync(0xFFFFFFFFu, mn, 8));
                mx = fmaxf(mx, __shfl_xor_sync(0xFFFFFFFFu, mx, 16));
                mn = fminf(mn, __shfl_xor_sync(0xFFFFFFFFu, mn, 16));
                if (g == 0) {
                    int col = col0 + wn * 64 + j * 8 + t * 2 + rb;
                    g_mx[(size_t)bm * COUT + col] = mx;
                    g_mn[(size_t)bm * COUT + col] = mn;
                }
            }
        }
    }
    if (LAYER > 0) {
        #pragma unroll
        for (int j = 0; j < 8; j++) {
            #pragma unroll
            for (int rb = 0; rb < 2; rb++) {
                float s = 0.f, q2 = 0.f;
                #pragma unroll
                for (int i = 0; i < 2; i++) {
                    float v0 = acc[i][j][rb], v1 = acc[i][j][rb + 2];
                    s += v0 + v1;
                    q2 += v0 * v0 + v1 * v1;
                }
                s  += __shfl_xor_sync(0xFFFFFFFFu, s, 4);
                q2 += __shfl_xor_sync(0xFFFFFFFFu, q2, 4);
                s  += __shfl_xor_sync(0xFFFFFFFFu, s, 8);
                q2 += __shfl_xor_sync(0xFFFFFFFFu, q2, 8);
                s  += __shfl_xor_sync(0xFFFFFFFFu, s, 16);
                q2 += __shfl_xor_sync(0xFFFFFFFFu, q2, 16);
                if (g == 0) {
                    int cc = wn * 64 + j * 8 + t * 2 + rb;
                    atomicAdd(&sPs[cc], s);
                    atomicAdd(&sPq[cc], q2);
                }
            }
        }
        __syncthreads();
        if (tid < 128) {
            atomicAdd(&g_stats[sumOff + col0 + tid], sPs[tid]);
            atomicAdd(&g_stats[sqOff  + col0 + tid], sPq[tid]);
        }
    }
}

// final: BN3 finalize + affine max/min selection + relu; 4 bm rows per block
__global__ void k_final(const float* __restrict__ g3, const float* __restrict__ b3,
                        float* __restrict__ out) {
    int bm0 = blockIdx.x * 4;
    int tid = threadIdx.x;
    __shared__ float sSc[COUT], sBi[COUT];
    const float invP = 1.f / (float)Pp;
    for (int o = tid; o < COUT; o += 256) {
        float mean = g_stats[SUML0 + 2048 + o] * invP;
        float var  = fmaxf(g_stats[SUML0 + 2048 + 512 + o] * invP - mean * mean, 0.f);
        float s = g3[o] * rsqrtf(var + 1e-5f);
        sSc[o] = s;
        sBi[o] = b3[o] - mean * s;
    }
    __syncthreads();
    #pragma unroll
    for (int r = 0; r < 4; r++) {
        int bm = bm0 + r;
        for (int o = tid; o < COUT; o += 256) {
            float s = sSc[o];
            float v = (s >= 0.f) ? s * g_mx[(size_t)bm * COUT + o]
                                 : s * g_mn[(size_t)bm * COUT + o];
            out[(size_t)bm * COUT + o] = fmaxf(v + sBi[o], 0.f);
        }
    }
}

#define SMEM_DYN ((2 * NSTG * STGW + 512 + 256) * 4)

extern "C" void kernel_launch(void* const* d_in, const int* in_sizes, int n_in,
                              void* d_out, int out_size) {
    const float* ffps_xyz     = (const float*)d_in[0];
    const float* ffps_feature = (const float*)d_in[1];
    const float* backbone_xyz = (const float*)d_in[2];
    const float* backbone_feat= (const float*)d_in[3];
    const float* sw1 = (const float*)d_in[4];
    const float* sg1 = (const float*)d_in[5];
    const float* sb1 = (const float*)d_in[6];
    const float* sw2 = (const float*)d_in[7];
    const float* sg2 = (const float*)d_in[8];
    const float* sb2 = (const float*)d_in[9];
    const float* w1  = (const float*)d_in[10];
    const float* g1  = (const float*)d_in[11];
    const float* b1  = (const float*)d_in[12];
    const float* w2  = (const float*)d_in[13];
    const float* g2  = (const float*)d_in[14];
    const float* b2  = (const float*)d_in[15];
    const float* w3  = (const float*)d_in[16];
    const float* g3  = (const float*)d_in[17];
    const float* b3  = (const float*)d_in[18];
    float* out = (float*)d_out;

    cudaFuncSetAttribute(k_mma<0>, cudaFuncAttributeMaxDynamicSharedMemorySize, SMEM_DYN);
    cudaFuncSetAttribute(k_mma<1>, cudaFuncAttributeMaxDynamicSharedMemorySize, SMEM_DYN);
    cudaFuncSetAttribute(k_mma<2>, cudaFuncAttributeMaxDynamicSharedMemorySize, SMEM_DYN);

    // fork point: stats zero on main (capture) stream
    k_zero<<<(NSTATS + 255) / 256, 256>>>();
    cudaEventRecord(g_side.evF, 0);
    cudaStreamWaitEvent(g_side.s, g_side.evF, 0);

    // branch B (side stream): weight prep, then shift MLP + ball query
    k_prep<<<(COUT * COUT + 255) / 256, 256, 0, g_side.s>>>(w1, w2, w3);
    cudaEventRecord(g_side.evP, g_side.s);
    k_s1<<<dim3(Bb * (Mm / 32), 2), 256, 0, g_side.s>>>(ffps_feature, sw1);
    k_fin<<<1, 128, 0, g_side.s>>>(128, SUM1, SQ1, sg1, sb1, 0, (float)(Bb * Mm));
    k_s2<<<Bb * (Mm / 32), 256, 0, g_side.s>>>(sw2);
    k_fin<<<1, 32, 0, g_side.s>>>(3, SUM2, SQ2, sg2, sb2, 1, (float)(Bb * Mm));
    k_neigh<<<Bb * Mm, 256, 0, g_side.s>>>(ffps_xyz, backbone_xyz);
    cudaEventRecord(g_side.evJ, g_side.s);

    // branch A (main stream): transpose, wait weights, G precompute
    k_transpose<<<dim3(Nn / 32, Cc / 32, Bb), dim3(32, 8)>>>(backbone_feat);
    cudaStreamWaitEvent(0, g_side.evP, 0);
    k_mma<0><<<dim3(COUT / 128, (Bb * Nn) / 128), 256, SMEM_DYN>>>(nullptr, nullptr);

    // join, then the serial tail
    cudaStreamWaitEvent(0, g_side.evJ, 0);
    k_gat<<<Bb * Mm, 256>>>(backbone_xyz);
    k_mma<1><<<dim3(COUT / 128, Pp / 128), 256, SMEM_DYN>>>(g1, b1);
    k_mma<2><<<dim3(COUT / 128, Pp / 128), 256, SMEM_DYN>>>(g2, b2);
    k_final<<<Bb * Mm / 4, 256>>>(g3, b3, out);
}

// round 17
// speedup vs baseline: 1.0319x; 1.0319x over previous
#include <cuda_runtime.h>
#include <cuda_fp16.h>
#include <math.h>
#include <stdint.h>

#define Bb 4
#define Nn 16384
#define Mm 1024
#define Cc 256
#define Kk 32
#define Pp (Bb*Mm*Kk)
#define COUT 512

#define SUM1 0
#define SQ1  128
#define SUM2 256
#define SQ2  260
#define SUML0 264
#define NSTATS (264 + 3*1024)

__device__ __align__(128) __half g_featTh[(size_t)Bb*Nn*Cc];
__device__ __align__(128) __half g_G[(size_t)Bb*Nn*COUT];
__device__ __align__(128) __half g_Y1[(size_t)Pp*COUT];
__device__ __align__(128) __half g_Y2[(size_t)Pp*COUT];
__device__ __align__(128) float  g_mx[(size_t)Bb*Mm*COUT];
__device__ __align__(128) float  g_mn[(size_t)Bb*Mm*COUT];
__device__ __align__(128) float  g_h1[Bb*128*Mm];
__device__ __align__(128) float  g_h2[Bb*3*Mm];
__device__ __align__(128) float  g_q[Bb*Mm*3];
__device__ __align__(128) int    g_idx[Pp];
__device__ __align__(128) __half g_W1h[COUT*Cc];
__device__ __align__(128) float  g_W1x[3*COUT];
__device__ __align__(128) __half g_W2h[COUT*COUT];
__device__ __align__(128) __half g_W3h[COUT*COUT];
__device__ __align__(128) float  g_stats[NSTATS];
__device__ float g_sc1[128], g_bi1[128];
__device__ float g_sc2[4],   g_bi2[4];

// side stream + fork/join events, created once before harness checkpoints
struct SideStream {
    cudaStream_t s;
    cudaEvent_t evF, evJ;
    SideStream() {
        cudaStreamCreateWithFlags(&s, cudaStreamNonBlocking);
        cudaEventCreateWithFlags(&evF, cudaEventDisableTiming);
        cudaEventCreateWithFlags(&evJ, cudaEventDisableTiming);
    }
};
static SideStream g_side;

__device__ __forceinline__ float wredsum(float v) {
    #pragma unroll
    for (int o = 16; o > 0; o >>= 1) v += __shfl_xor_sync(0xFFFFFFFFu, v, o);
    return v;
}
__device__ __forceinline__ uint32_t packh2(float a, float b) {
    __half2 h = __floats2half2_rn(a, b);
    return *(uint32_t*)&h;
}
__device__ __forceinline__ uint32_t smem_u32(const void* p) {
    uint32_t a;
    asm("{ .reg .u64 t; cvta.to.shared.u64 t, %1; cvt.u32.u64 %0, t; }" : "=r"(a) : "l"(p));
    return a;
}
__device__ __forceinline__ void mma_f16(float* d, const uint32_t* a, const uint32_t* b) {
    asm volatile("mma.sync.aligned.m16n8k16.row.col.f32.f16.f16.f32 "
                 "{%0,%1,%2,%3}, {%4,%5,%6,%7}, {%8,%9}, {%0,%1,%2,%3};"
                 : "+f"(d[0]), "+f"(d[1]), "+f"(d[2]), "+f"(d[3])
                 : "r"(a[0]), "r"(a[1]), "r"(a[2]), "r"(a[3]), "r"(b[0]), "r"(b[1]));
}
__device__ __forceinline__ void ldsm_x4(uint32_t& r0, uint32_t& r1, uint32_t& r2, uint32_t& r3, uint32_t addr) {
    asm volatile("ldmatrix.sync.aligned.m8n8.x4.shared.b16 {%0,%1,%2,%3}, [%4];"
                 : "=r"(r0), "=r"(r1), "=r"(r2), "=r"(r3) : "r"(addr));
}
__device__ __forceinline__ void cpa16(uint32_t dst, const void* src) {
    asm volatile("cp.async.cg.shared.global [%0], [%1], 16;" :: "r"(dst), "l"(src));
}
#define CPA_COMMIT() asm volatile("cp.async.commit_group;" ::: "memory")
#define CPA_WAIT1()  asm volatile("cp.async.wait_group 1;" ::: "memory")

// prep: zero stats + repack w1 (split feat/xyz) + convert w2/w3 to fp16
__global__ void k_prep(const float* __restrict__ w1, const float* __restrict__ w2,
                       const float* __restrict__ w3) {
    int i = blockIdx.x * blockDim.x + threadIdx.x;
    if (i < NSTATS) g_stats[i] = 0.f;
    if (i < COUT * Cc) {
        int o = i >> 8, c = i & 255;
        g_W1h[i] = __float2half(w1[o * 259 + 3 + c]);
    }
    if (i < 3 * COUT) {
        int d = i / COUT, o = i % COUT;
        g_W1x[d * COUT + o] = w1[o * 259 + d];
    }
    if (i < COUT * COUT) {
        g_W2h[i] = __float2half(w2[i]);
        g_W3h[i] = __float2half(w3[i]);
    }
}

// grid (128, 2): blk.x = b(4)*mtile(32), blk.y = o-half; 256 thr
__global__ void k_s1(const float* __restrict__ feat, const float* __restrict__ sw1) {
    int blk = blockIdx.x;
    int b = blk >> 5;
    int m0 = (blk & 31) * 32;
    int ob = blockIdx.y * 64;
    int tid = threadIdx.x;
    int mx = tid & 31, oy = tid >> 5;
    __shared__ float s_w[64][17];
    __shared__ float s_f[16][33];
    float acc[8];
    #pragma unroll
    for (int r = 0; r < 8; r++) acc[r] = 0.f;
    for (int c0 = 0; c0 < 256; c0 += 16) {
        __syncthreads();
        for (int idx = tid; idx < 64 * 16; idx += 256) {
            int ol = idx >> 4, kk = idx & 15;
            s_w[ol][kk] = sw1[(ob + ol) * 256 + c0 + kk];
        }
        for (int idx = tid; idx < 16 * 32; idx += 256) {
            int kk = idx >> 5, mm = idx & 31;
            s_f[kk][mm] = feat[((size_t)b * 256 + c0 + kk) * Mm + m0 + mm];
        }
        __syncthreads();
        #pragma unroll
        for (int r = 0; r < 8; r++) {
            int ol = oy * 8 + r;
            #pragma unroll
            for (int kk = 0; kk < 16; kk++) acc[r] += s_w[ol][kk] * s_f[kk][mx];
        }
    }
    #pragma unroll
    for (int r = 0; r < 8; r++) {
        int o = ob + oy * 8 + r;
        float v = acc[r];
        g_h1[((size_t)b * 128 + o) * Mm + m0 + mx] = v;
        float s = wredsum(v), s2 = wredsum(v * v);
        if (mx == 0) {
            atomicAdd(&g_stats[SUM1 + o], s);
            atomicAdd(&g_stats[SQ1 + o], s2);
        }
    }
}

__global__ void k_fin(int n, int sumOff, int sqOff,
                      const float* __restrict__ gamma, const float* __restrict__ beta,
                      int which, float count) {
    int i = blockIdx.x * blockDim.x + threadIdx.x;
    if (i >= n) return;
    float mean = g_stats[sumOff + i] / count;
    float var  = g_stats[sqOff + i] / count - mean * mean;
    var = fmaxf(var, 0.f);
    float s = gamma[i] * rsqrtf(var + 1e-5f);
    float bi = beta[i] - mean * s;
    if (which == 0) { g_sc1[i] = s; g_bi1[i] = bi; }
    else            { g_sc2[i] = s; g_bi2[i] = bi; }
}

// grid 128 (b*mtile32), 256 thr: 8 o-groups of 16 x 32 m; smem reduce
__global__ void k_s2(const float* __restrict__ sw2) {
    int blk = blockIdx.x;
    int b = blk >> 5;
    int m0 = (blk & 31) * 32;
    int tid = threadIdx.x;
    int mx = tid & 31, og = tid >> 5;
    __shared__ float s_w[3][128];
    __shared__ float red[3][8][33];
    for (int i = tid; i < 384; i += 256) s_w[i >> 7][i & 127] = sw2[i];
    __syncthreads();
    float a0 = 0.f, a1 = 0.f, a2 = 0.f;
    #pragma unroll
    for (int oo = 0; oo < 16; oo++) {
        int o = og * 16 + oo;
        float h = g_h1[((size_t)b * 128 + o) * Mm + m0 + mx];
        float x = fmaxf(h * g_sc1[o] + g_bi1[o], 0.f);
        a0 += s_w[0][o] * x;
        a1 += s_w[1][o] * x;
        a2 += s_w[2][o] * x;
    }
    red[0][og][mx] = a0;
    red[1][og][mx] = a1;
    red[2][og][mx] = a2;
    __syncthreads();
    if (og < 3) {
        float tt = 0.f;
        #pragma unroll
        for (int w = 0; w < 8; w++) tt += red[og][w][mx];
        int m = m0 + mx;
        g_h2[((size_t)b * 3 + og) * Mm + m] = tt;
        float s = wredsum(tt), ss = wredsum(tt * tt);
        if (mx == 0) {
            atomicAdd(&g_stats[SUM2 + og], s);
            atomicAdd(&g_stats[SQ2 + og], ss);
        }
    }
}

__global__ void k_neigh(const float* __restrict__ fxyz, const float* __restrict__ bxyz) {
    int bm = blockIdx.x;
    int b = bm >> 10;
    int m = bm & 1023;
    int tid = threadIdx.x;
    __shared__ float q[3];
    __shared__ int list[Kk];
    __shared__ int cnt;
    __shared__ unsigned masks[8];
    if (tid == 0) cnt = 0;
    if (tid < 3) {
        float h = g_h2[((size_t)b * 3 + tid) * Mm + m];
        float sft = fmaxf(h * g_sc2[tid] + g_bi2[tid], 0.f);
        float qq = fxyz[((size_t)b * Mm + m) * 3 + tid] + sft;
        q[tid] = qq;
        g_q[((size_t)b * Mm + m) * 3 + tid] = qq;
    }
    __syncthreads();
    float qx = q[0], qy = q[1], qz = q[2];
    const float* bx = bxyz + (size_t)b * Nn * 3;
    int lane = tid & 31, wid = tid >> 5;
    for (int ch = 0; ch < Nn / 256; ch++) {
        int j = ch * 256 + tid;
        float dx = bx[j * 3 + 0] - qx;
        float dy = bx[j * 3 + 1] - qy;
        float dz = bx[j * 3 + 2] - qz;
        bool p = (dx * dx + dy * dy + dz * dz) < 1.0f;
        unsigned mk = __ballot_sync(0xFFFFFFFFu, p);
        if (lane == 0) masks[wid] = mk;
        __syncthreads();
        int before = cnt;
        for (int w = 0; w < wid; w++) before += __popc(masks[w]);
        if (p) {
            int pos = before + __popc(mk & ((1u << lane) - 1u));
            if (pos < Kk) list[pos] = j;
        }
        int total = 0;
        #pragma unroll
        for (int w = 0; w < 8; w++) total += __popc(masks[w]);
        __syncthreads();
        if (tid == 0) cnt += total;
        __syncthreads();
        if (cnt >= Kk) break;
    }
    if (tid < Kk) {
        int c = cnt;
        int v;
        if (c == 0)        v = 0;
        else if (tid < c)  v = list[tid];
        else               v = list[0];
        g_idx[bm * Kk + tid] = v;
    }
}

// transpose (B,C,N) f32 -> (B,N,C) fp16, half2 stores
__global__ void k_transpose(const float* __restrict__ bf) {
    __shared__ float t[32][33];
    int b = blockIdx.z;
    int j0 = blockIdx.x * 32;
    int c0 = blockIdx.y * 32;
    int x = threadIdx.x, y = threadIdx.y;
    #pragma unroll
    for (int yy = y; yy < 32; yy += 8)
        t[yy][x] = bf[((size_t)b * Cc + c0 + yy) * Nn + j0 + x];
    __syncthreads();
    int tid = y * 32 + x;
    #pragma unroll
    for (int idx = tid; idx < 32 * 16; idx += 256) {
        int j = idx >> 4, cp = idx & 15;
        __half2 h = __floats2half2_rn(t[cp * 2][j], t[cp * 2 + 1][j]);
        *(__half2*)(g_featTh + ((size_t)b * Nn + j0 + j) * Cc + c0 + cp * 2) = h;
    }
}

// gather-add: Y0[p,:] = G[b,j_p,:] + W1x @ dx; BN0 stats fused
__global__ void k_gat(const float* __restrict__ bxyz) {
    int bm = blockIdx.x;
    int b = bm >> 10;
    int tid = threadIdx.x;
    __shared__ int jl[Kk];
    __shared__ float dxs[3][Kk];
    if (tid < Kk) {
        int j = g_idx[bm * Kk + tid];
        jl[tid] = j;
        const float* bx = bxyz + ((size_t)b * Nn + j) * 3;
        dxs[0][tid] = bx[0] - g_q[bm * 3 + 0];
        dxs[1][tid] = bx[1] - g_q[bm * 3 + 1];
        dxs[2][tid] = bx[2] - g_q[bm * 3 + 2];
    }
    __syncthreads();
    float2 wx0 = *(const float2*)&g_W1x[0 * COUT + 2 * tid];
    float2 wx1 = *(const float2*)&g_W1x[1 * COUT + 2 * tid];
    float2 wx2 = *(const float2*)&g_W1x[2 * COUT + 2 * tid];
    float s0 = 0.f, s1 = 0.f, q20 = 0.f, q21 = 0.f;
    #pragma unroll 4
    for (int k = 0; k < Kk; k++) {
        int j = jl[k];
        __half2 gh = *(const __half2*)(g_G + (((size_t)b * Nn + j) << 9) + 2 * tid);
        float2 gf = __half22float2(gh);
        float d0 = dxs[0][k], d1 = dxs[1][k], d2 = dxs[2][k];
        float y0 = gf.x + wx0.x * d0 + wx1.x * d1 + wx2.x * d2;
        float y1 = gf.y + wx0.y * d0 + wx1.y * d1 + wx2.y * d2;
        *(uint32_t*)(g_Y1 + (((size_t)(bm * Kk + k)) << 9) + 2 * tid) = packh2(y0, y1);
        s0 += y0; s1 += y1;
        q20 += y0 * y0; q21 += y1 * y1;
    }
    atomicAdd(&g_stats[SUML0 + 2 * tid],       s0);
    atomicAdd(&g_stats[SUML0 + 2 * tid + 1],   s1);
    atomicAdd(&g_stats[SUML0 + 512 + 2 * tid],     q20);
    atomicAdd(&g_stats[SUML0 + 512 + 2 * tid + 1], q21);
}

#define NSTG 3
#define LD2 20
#define STGW (128 * LD2)

// f32-acc GEMM. LAYER 0: G = featTh @ W1h^T (no BN in, no stats out).
// LAYER 1: Y2 = relu(bn0(Y1)) @ W2^T.
// LAYER 2: per-(bm,col) max/min of relu(bn1(Y2)) @ W3^T  (no Y store).
template <int LAYER>
__global__ void __launch_bounds__(256, 2) k_mma(const float* __restrict__ gamPrev,
                                                const float* __restrict__ betPrev) {
    constexpr int CIN = (LAYER == 0) ? Cc : COUT;
    constexpr int NCH = CIN / 32;
    constexpr int sumOff = SUML0 + LAYER * 1024;
    constexpr int sqOff  = sumOff + 512;
    const __half* Ah = (LAYER == 0) ? g_featTh : (LAYER == 1 ? g_Y1 : g_Y2);
    __half*       Y  = (LAYER == 0) ? g_G     : g_Y2;
    const __half* W  = (LAYER == 0) ? g_W1h   : (LAYER == 1 ? g_W2h : g_W3h);

    extern __shared__ uint32_t dyn[];
    uint32_t* sA   = dyn;
    uint32_t* sB   = dyn + NSTG * STGW;
    uint32_t* sSc2 = dyn + 2 * NSTG * STGW;
    uint32_t* sBi2 = sSc2 + 256;
    float*    sPs  = (float*)(sBi2 + 256);
    float*    sPq  = sPs + 128;

    int tid = threadIdx.x;
    int lane = tid & 31, wrp = tid >> 5;
    int g = lane >> 2, t = lane & 3;
    int wm = wrp & 3, wn = wrp >> 2;
    int row0 = blockIdx.y * 128;
    int col0 = blockIdx.x * 128;

    if (LAYER > 0) {
        const float invP = 1.f / (float)Pp;
        int pOff = SUML0 + (LAYER - 1) * 1024;
        for (int cp = tid; cp < 256; cp += 256) {
            int c0 = cp * 2, c1 = cp * 2 + 1;
            float m0 = g_stats[pOff + c0] * invP;
            float v0 = fmaxf(g_stats[pOff + 512 + c0] * invP - m0 * m0, 0.f);
            float s0 = gamPrev[c0] * rsqrtf(v0 + 1e-5f);
            float m1 = g_stats[pOff + c1] * invP;
            float v1 = fmaxf(g_stats[pOff + 512 + c1] * invP - m1 * m1, 0.f);
            float s1 = gamPrev[c1] * rsqrtf(v1 + 1e-5f);
            sSc2[cp] = packh2(s0, s1);
            sBi2[cp] = packh2(betPrev[c0] - m0 * s0, betPrev[c1] - m1 * s1);
        }
        if (tid < 128) { sPs[tid] = 0.f; sPq[tid] = 0.f; }
        __syncthreads();
    }

    int r0 = tid >> 2, q0 = tid & 3;
    int r1 = r0 + 64;
    const char* aSrc0 = (const char*)(Ah + (size_t)(row0 + r0) * CIN) + q0 * 16;
    const char* aSrc1 = (const char*)(Ah + (size_t)(row0 + r1) * CIN) + q0 * 16;
    const char* bSrc0 = (const char*)(W + (size_t)(col0 + r0) * CIN) + q0 * 16;
    const char* bSrc1 = (const char*)(W + (size_t)(col0 + r1) * CIN) + q0 * 16;
    uint32_t sbA = smem_u32(sA), sbB = smem_u32(sB);
    uint32_t aDst0 = sbA + (r0 * LD2 + q0 * 4) * 4;
    uint32_t aDst1 = sbA + (r1 * LD2 + q0 * 4) * 4;
    uint32_t bDst0 = sbB + (r0 * LD2 + q0 * 4) * 4;
    uint32_t bDst1 = sbB + (r1 * LD2 + q0 * 4) * 4;

    uint32_t aoff[2], boff[4];
    #pragma unroll
    for (int i = 0; i < 2; i++)
        aoff[i] = ((wm * 32 + i * 16 + (lane & 15)) * LD2 + (lane >> 4) * 4) * 4;
    #pragma unroll
    for (int jp = 0; jp < 4; jp++)
        boff[jp] = ((wn * 64 + jp * 16 + ((lane >> 4) & 1) * 8 + (lane & 7)) * LD2
                    + ((lane >> 3) & 1) * 4) * 4;

    float acc[2][8][4];
    #pragma unroll
    for (int i = 0; i < 2; i++)
        #pragma unroll
        for (int j = 0; j < 8; j++)
            #pragma unroll
            for (int rr = 0; rr < 4; rr++) acc[i][j][rr] = 0.f;

    auto fill = [&](int c) {
        int s = c % NSTG;
        uint32_t so = (uint32_t)s * (STGW * 4);
        cpa16(aDst0 + so, aSrc0 + c * 64);
        cpa16(aDst1 + so, aSrc1 + c * 64);
        cpa16(bDst0 + so, bSrc0 + c * 64);
        cpa16(bDst1 + so, bSrc1 + c * 64);
    };

    const __half2 z2 = __float2half2_rn(0.f);
    fill(0); CPA_COMMIT();
    fill(1); CPA_COMMIT();

    for (int c = 0; c < NCH; c++) {
        CPA_WAIT1();
        __syncthreads();
        int s = c % NSTG;
        uint32_t aB = sbA + (uint32_t)s * (STGW * 4);
        uint32_t bB = sbB + (uint32_t)s * (STGW * 4);
        uint32_t scw[2][2], biw[2][2];
        if (LAYER > 0) {
            #pragma unroll
            for (int ks = 0; ks < 2; ks++)
                #pragma unroll
                for (int sub = 0; sub < 2; sub++) {
                    int idx = c * 16 + ks * 8 + sub * 4 + t;
                    scw[ks][sub] = sSc2[idx];
                    biw[ks][sub] = sBi2[idx];
                }
        }
        #pragma unroll
        for (int ks = 0; ks < 2; ks++) {
            uint32_t af[2][4], bf[8][2];
            #pragma unroll
            for (int i = 0; i < 2; i++)
                ldsm_x4(af[i][0], af[i][1], af[i][2], af[i][3], aB + aoff[i] + ks * 32);
            #pragma unroll
            for (int jp = 0; jp < 4; jp++)
                ldsm_x4(bf[jp * 2][0], bf[jp * 2][1], bf[jp * 2 + 1][0], bf[jp * 2 + 1][1],
                        bB + boff[jp] + ks * 32);
            if (LAYER > 0) {
                #pragma unroll
                for (int i = 0; i < 2; i++)
                    #pragma unroll
                    for (int rr = 0; rr < 4; rr++) {
                        int sub = rr >> 1;
                        __half2 h = *(__half2*)&af[i][rr];
                        h = __hmax2(__hfma2(h, *(__half2*)&scw[ks][sub], *(__half2*)&biw[ks][sub]), z2);
                        af[i][rr] = *(uint32_t*)&h;
                    }
            }
            #pragma unroll
            for (int i = 0; i < 2; i++)
                #pragma unroll
                for (int j = 0; j < 8; j++)
                    mma_f16(acc[i][j], af[i], bf[j]);
        }
        if (c + 2 < NCH) fill(c + 2);
        CPA_COMMIT();
    }

    if (LAYER != 2) {
        #pragma unroll
        for (int i = 0; i < 2; i++) {
            int rlo = row0 + wm * 32 + i * 16 + g;
            #pragma unroll
            for (int j = 0; j < 8; j++) {
                int col = col0 + wn * 64 + j * 8 + t * 2;
                *(uint32_t*)(Y + (size_t)rlo * COUT + col)       = packh2(acc[i][j][0], acc[i][j][1]);
                *(uint32_t*)(Y + (size_t)(rlo + 8) * COUT + col) = packh2(acc[i][j][2], acc[i][j][3]);
            }
        }
    } else {
        int bm = blockIdx.y * 4 + wm;
        #pragma unroll
        for (int j = 0; j < 8; j++) {
            #pragma unroll
            for (int rb = 0; rb < 2; rb++) {
                float mx = fmaxf(fmaxf(acc[0][j][rb], acc[0][j][rb + 2]),
                                 fmaxf(acc[1][j][rb], acc[1][j][rb + 2]));
                float mn = fminf(fminf(acc[0][j][rb], acc[0][j][rb + 2]),
                                 fminf(acc[1][j][rb], acc[1][j][rb + 2]));
                mx = fmaxf(mx, __shfl_xor_sync(0xFFFFFFFFu, mx, 4));
                mn = fminf(mn, __shfl_xor_sync(0xFFFFFFFFu, mn, 4));
                mx = fmaxf(mx, __shfl_xor_sync(0xFFFFFFFFu, mx, 8));
                mn = fminf(mn, __shfl_xor_sync(0xFFFFFFFFu, mn, 8));
                mx = fmaxf(mx, __shfl_xor_sync(0xFFFFFFFFu, mx, 16));
                mn = fminf(mn, __shfl_xor_sync(0xFFFFFFFFu, mn, 16));
                if (g == 0) {
                    int col = col0 + wn * 64 + j * 8 + t * 2 + rb;
                    g_mx[(size_t)bm * COUT + col] = mx;
                    g_mn[(size_t)bm * COUT + col] = mn;
                }
            }
        }
    }
    if (LAYER > 0) {
        #pragma unroll
        for (int j = 0; j < 8; j++) {
            #pragma unroll
            for (int rb = 0; rb < 2; rb++) {
                float s = 0.f, q2 = 0.f;
                #pragma unroll
                for (int i = 0; i < 2; i++) {
                    float v0 = acc[i][j][rb], v1 = acc[i][j][rb + 2];
                    s += v0 + v1;
                    q2 += v0 * v0 + v1 * v1;
                }
                s  += __shfl_xor_sync(0xFFFFFFFFu, s, 4);
                q2 += __shfl_xor_sync(0xFFFFFFFFu, q2, 4);
                s  += __shfl_xor_sync(0xFFFFFFFFu, s, 8);
                q2 += __shfl_xor_sync(0xFFFFFFFFu, q2, 8);
                s  += __shfl_xor_sync(0xFFFFFFFFu, s, 16);
                q2 += __shfl_xor_sync(0xFFFFFFFFu, q2, 16);
                if (g == 0) {
                    int cc = wn * 64 + j * 8 + t * 2 + rb;
                    atomicAdd(&sPs[cc], s);
                    atomicAdd(&sPq[cc], q2);
                }
            }
        }
        __syncthreads();
        if (tid < 128) {
            atomicAdd(&g_stats[sumOff + col0 + tid], sPs[tid]);
            atomicAdd(&g_stats[sqOff  + col0 + tid], sPq[tid]);
        }
    }
}

// final: BN3 finalize + affine max/min selection + relu; 4 bm rows per block
__global__ void k_final(const float* __restrict__ g3, const float* __restrict__ b3,
                        float* __restrict__ out) {
    int bm0 = blockIdx.x * 4;
    int tid = threadIdx.x;
    __shared__ float sSc[COUT], sBi[COUT];
    const float invP = 1.f / (float)Pp;
    for (int o = tid; o < COUT; o += 256) {
        float mean = g_stats[SUML0 + 2048 + o] * invP;
        float var  = fmaxf(g_stats[SUML0 + 2048 + 512 + o] * invP - mean * mean, 0.f);
        float s = g3[o] * rsqrtf(var + 1e-5f);
        sSc[o] = s;
        sBi[o] = b3[o] - mean * s;
    }
    __syncthreads();
    #pragma unroll
    for (int r = 0; r < 4; r++) {
        int bm = bm0 + r;
        for (int o = tid; o < COUT; o += 256) {
            float s = sSc[o];
            float v = (s >= 0.f) ? s * g_mx[(size_t)bm * COUT + o]
                                 : s * g_mn[(size_t)bm * COUT + o];
            out[(size_t)bm * COUT + o] = fmaxf(v + sBi[o], 0.f);
        }
    }
}

#define SMEM_DYN ((2 * NSTG * STGW + 512 + 256) * 4)

extern "C" void kernel_launch(void* const* d_in, const int* in_sizes, int n_in,
                              void* d_out, int out_size) {
    const float* ffps_xyz     = (const float*)d_in[0];
    const float* ffps_feature = (const float*)d_in[1];
    const float* backbone_xyz = (const float*)d_in[2];
    const float* backbone_feat= (const float*)d_in[3];
    const float* sw1 = (const float*)d_in[4];
    const float* sg1 = (const float*)d_in[5];
    const float* sb1 = (const float*)d_in[6];
    const float* sw2 = (const float*)d_in[7];
    const float* sg2 = (const float*)d_in[8];
    const float* sb2 = (const float*)d_in[9];
    const float* w1  = (const float*)d_in[10];
    const float* g1  = (const float*)d_in[11];
    const float* b1  = (const float*)d_in[12];
    const float* w2  = (const float*)d_in[13];
    const float* g2  = (const float*)d_in[14];
    const float* b2  = (const float*)d_in[15];
    const float* w3  = (const float*)d_in[16];
    const float* g3  = (const float*)d_in[17];
    const float* b3  = (const float*)d_in[18];
    float* out = (float*)d_out;

    cudaFuncSetAttribute(k_mma<0>, cudaFuncAttributeMaxDynamicSharedMemorySize, SMEM_DYN);
    cudaFuncSetAttribute(k_mma<1>, cudaFuncAttributeMaxDynamicSharedMemorySize, SMEM_DYN);
    cudaFuncSetAttribute(k_mma<2>, cudaFuncAttributeMaxDynamicSharedMemorySize, SMEM_DYN);

    // fork point: combined stats-zero + weight prep on main (capture) stream
    k_prep<<<(COUT * COUT + 255) / 256, 256>>>(w1, w2, w3);
    cudaEventRecord(g_side.evF, 0);
    cudaStreamWaitEvent(g_side.s, g_side.evF, 0);

    // branch B (side stream): shift MLP + ball query
    k_s1<<<dim3(Bb * (Mm / 32), 2), 256, 0, g_side.s>>>(ffps_feature, sw1);
    k_fin<<<1, 128, 0, g_side.s>>>(128, SUM1, SQ1, sg1, sb1, 0, (float)(Bb * Mm));
    k_s2<<<Bb * (Mm / 32), 256, 0, g_side.s>>>(sw2);
    k_fin<<<1, 32, 0, g_side.s>>>(3, SUM2, SQ2, sg2, sb2, 1, (float)(Bb * Mm));
    k_neigh<<<Bb * Mm, 256, 0, g_side.s>>>(ffps_xyz, backbone_xyz);
    cudaEventRecord(g_side.evJ, g_side.s);

    // branch A (main stream): transpose + G precompute
    k_transpose<<<dim3(Nn / 32, Cc / 32, Bb), dim3(32, 8)>>>(backbone_feat);
    k_mma<0><<<dim3(COUT / 128, (Bb * Nn) / 128), 256, SMEM_DYN>>>(nullptr, nullptr);

    // join, then the serial tail
    cudaStreamWaitEvent(0, g_side.evJ, 0);
    k_gat<<<Bb * Mm, 256>>>(backbone_xyz);
    k_mma<1><<<dim3(COUT / 128, Pp / 128), 256, SMEM_DYN>>>(g1, b1);
    k_mma<2><<<dim3(COUT / 128, Pp / 128), 256, SMEM_DYN>>>(g2, b2);
    k_final<<<Bb * Mm / 4, 256>>>(g3, b3, out);
}